// round 15
// baseline (speedup 1.0000x reference)
#include <cuda_runtime.h>
#include <cstdint>

#define HID   100
#define GXS   512
#define TENC  4096
#define TDEC  4096
#define NCLS  6
#define NTH   416          // 13 warps; warps 0-11 + warp12 lanes 0-15: one gate-row per lane
#define LOG2E 1.4426950408889634f

typedef unsigned long long ull;

// per-step input contributions; slot = 32*(u>>3) + ((u&7)<<2) + gt  (u unit, gt gate)
// slots 400-511 never written -> stay zero (logits/dummy lanes read them)
__device__ float g_gge[TENC * GXS];
__device__ float g_ggd[TDEC * GXS];

// ---- packed f32x2 / math helpers ----
__device__ __forceinline__ ull fma2(ull a, ull b, ull c) {
    ull d;
    asm("fma.rn.f32x2 %0, %1, %2, %3;" : "=l"(d) : "l"(a), "l"(b), "l"(c));
    return d;
}
__device__ __forceinline__ ull add2(ull a, ull b) {
    ull d;
    asm("add.rn.f32x2 %0, %1, %2;" : "=l"(d) : "l"(a), "l"(b));
    return d;
}
__device__ __forceinline__ float ex2f(float x) {
    float y; asm("ex2.approx.f32 %0, %1;" : "=f"(y) : "f"(x)); return y;
}
__device__ __forceinline__ float rcpf(float x) {
    float y; asm("rcp.approx.f32 %0, %1;" : "=f"(y) : "f"(x)); return y;
}
__device__ __forceinline__ float tanhf_fast(float x) {
    return 1.0f - 2.0f * rcpf(1.0f + ex2f((2.0f * LOG2E) * x));
}
__device__ __forceinline__ float hsum2(ull s) {
    float lo, hi;
    asm("mov.b64 {%0,%1},%2;" : "=f"(lo), "=f"(hi) : "l"(s));
    return lo + hi;
}

// One 100-col row dot, 3-deep pipelined LDS.128, 2 accumulators, gx in acc init.
// Lean on registers: 12 buf regs + 4 acc regs.
__device__ __forceinline__ float dotsingle(const ull (&w)[50], unsigned hb, float gx) {
    ull bx[3], by[3];
#pragma unroll
    for (int m = 0; m < 3; ++m)
        asm volatile("ld.shared.v2.b64 {%0,%1},[%2];"
                     : "=l"(bx[m]), "=l"(by[m]) : "r"(hb + 16u * m));
    ull a0, a1 = 0ull;
    asm("mov.b64 %0,{%1,%2};" : "=l"(a0) : "f"(gx), "f"(0.0f));
#pragma unroll
    for (int m = 0; m < 25; ++m) {
        const int sl = m % 3;
        a0 = fma2(w[2 * m],     bx[sl], a0);
        a1 = fma2(w[2 * m + 1], by[sl], a1);
        if (m + 3 < 25)
            asm volatile("ld.shared.v2.b64 {%0,%1},[%2];"
                         : "=l"(bx[sl]), "=l"(by[sl]) : "r"(hb + 16u * (m + 3)));
    }
    return hsum2(add2(a0, a1));
}

// ---------------- prep kernel: gx precompute (fully parallel) ----------------
__global__ void gx_prep_kernel(const float* __restrict__ x,     // [TENC,3]
                               const int*   __restrict__ y,     // [TDEC]
                               const float* __restrict__ eWih,
                               const float* __restrict__ ebih,
                               const float* __restrict__ ebhh,
                               const float* __restrict__ dWih,
                               const float* __restrict__ dbih,
                               const float* __restrict__ dbhh)
{
    int idx = blockIdx.x * blockDim.x + threadIdx.x;
    if (idx >= TENC * 400) return;
    int t = idx / 400;
    int r = idx - t * 400;
    int u = r % 100, gt = r / 100;
    int slot = 32 * (u >> 3) + ((u & 7) << 2) + gt;   // <= 399
    int dst = t * GXS + slot;
    g_gge[dst] = ebih[r] + ebhh[r]
               + x[3*t+0] * eWih[3*r+0]
               + x[3*t+1] * eWih[3*r+1]
               + x[3*t+2] * eWih[3*r+2];
    g_ggd[dst] = dbih[r] + dbhh[r] + (float)y[t] * dWih[r];
}

// ---- weight load: row lanes get Whh row; logits/dummy lanes get linW row ----
__device__ __forceinline__ void load_w(const float* __restrict__ Whh,
                                       const float* __restrict__ linW,
                                       int wid, int lane, bool rowlane,
                                       ull (&w)[50])
{
    const float* src;
    if (rowlane) {
        const int u = 8 * wid + (lane >> 2);
        const int gt = lane & 3;
        src = Whh + (u + gt * HID) * HID;
    } else {
        int cls = lane - 16; if (cls > 5) cls = 5;
        src = linW + cls * HID;
    }
    const ull* p = (const ull*)src;
#pragma unroll
    for (int k = 0; k < 50; ++k) w[k] = p[k];
}

// ---- one step: uniform dot for every lane; short role-specific epilogue ----
template<bool DEC>
__device__ __forceinline__ void step(
    int s, int TW, const float* __restrict__ gg,
    const ull (&w)[50], unsigned hbR, float* __restrict__ hW,
    float& gx, float& c, float aa, float lb,
    int tid, int wid, int lane, unsigned mvmask, bool rowlane,
    float* __restrict__ out)
{
    int sn = s + 1; if (sn > TW - 1) sn = TW - 1;
    const float nx = __ldg(gg + sn * GXS + tid);      // prefetch, hidden under dot
    const float d = dotsingle(w, hbR, gx);
    if (rowlane) {
        // act consts from aa (1 = tanh gate g, 0 = sigmoid): bb = 1-3aa, kk = (3aa-1)*LOG2E
        const float bb = fmaf(-3.0f, aa, 1.0f);
        const float kk = LOG2E * fmaf(3.0f, aa, -1.0f);
        const float act = fmaf(bb, rcpf(1.0f + ex2f(kk * d)), aa);
        const int base = lane & ~3;
        const float iv = __shfl_sync(mvmask, act, base);
        const float fv = __shfl_sync(mvmask, act, base + 1);
        const float gv = __shfl_sync(mvmask, act, base + 2);
        const float ov = __shfl_sync(mvmask, act, base + 3);
        c = fmaf(fv, c, iv * gv);                     // redundant on all 4 lanes
        const float h = ov * tanhf_fast(c);
        if ((lane & 3) == 0) hW[8 * wid + (lane >> 2)] = h;
    } else if (DEC && s >= 1) {
        const int cls = lane - 16;
        if (cls < NCLS) out[(s - 1) * NCLS + cls] = d + lb;
    }
    gx = nx;
}

// ---------------- persistent recurrence kernel ----------------
__global__ void __launch_bounds__(NTH, 1)
lstm_encdec_kernel(const float* __restrict__ eWhh,   // [400,100]
                   const float* __restrict__ dWhh,   // [400,100]
                   const float* __restrict__ linW,   // [6,100]
                   const float* __restrict__ linb,   // [6]
                   float* __restrict__ out)          // [TDEC,6]
{
    __shared__ __align__(1024) float hbuf[2][128];

    const int tid  = threadIdx.x;
    const int wid  = tid >> 5;
    const int lane = tid & 31;
    const bool rowlane = (wid < 12) || (lane < 16);
    const unsigned mvmask = (wid == 12) ? 0x0000FFFFu : 0xFFFFFFFFu;

    // ---- init ----
    if (tid < 128) { hbuf[0][tid] = 0.0f; hbuf[1][tid] = 0.0f; }
    if (tid < NCLS) out[(TDEC - 1) * NCLS + tid] = 0.0f;

    // aa = 1 for the tanh gate (gt==2) on row lanes
    const float aa = (rowlane && (lane & 3) == 2) ? 1.0f : 0.0f;
    float lb = 0.0f;
    if (!rowlane) {
        int cls = lane - 16; if (cls > 5) cls = 5;
        lb = linb[cls];
    }

    // ---- encoder weights ----
    ull w[50];
    load_w(eWhh, linW, wid, lane, rowlane, w);
    float c = 0.0f;
    __syncthreads();

    const unsigned hb0 = (unsigned)__cvta_generic_to_shared(&hbuf[0][0]);
    const unsigned hb1 = hb0 + 512u;
    float* const h0 = &hbuf[0][0];
    float* const h1 = &hbuf[1][0];

    float gx = __ldg(g_gge + tid);

    // ================= encoder: 4096 steps =================
#pragma unroll 1
    for (int it = 0; it < TENC / 2; ++it) {
        step<false>(2 * it,     TENC, g_gge, w, hb0, h1, gx, c, aa, lb,
                    tid, wid, lane, mvmask, rowlane, out);
        __syncthreads();
        step<false>(2 * it + 1, TENC, g_gge, w, hb1, h0, gx, c, aa, lb,
                    tid, wid, lane, mvmask, rowlane, out);
        __syncthreads();
    }
    // h_enc in hbuf[0]

    // ---- decoder weights (registers only; logits lanes reload same linW) ----
    load_w(dWhh, linW, wid, lane, rowlane, w);
    gx = __ldg(g_ggd + tid);

    // ================= decoder: 4095 work steps =================
    const int TW = TDEC - 1;   // 4095
#pragma unroll 1
    for (int it = 0; it < (TW - 1) / 2; ++it) {       // steps 0..4093
        step<true>(2 * it,     TW, g_ggd, w, hb0, h1, gx, c, aa, lb,
                   tid, wid, lane, mvmask, rowlane, out);
        __syncthreads();
        step<true>(2 * it + 1, TW, g_ggd, w, hb1, h0, gx, c, aa, lb,
                   tid, wid, lane, mvmask, rowlane, out);
        __syncthreads();
    }
    // step 4094: reads hbuf[0] -> writes hbuf[1]; emits logits row 4093
    step<true>(TW - 1, TW, g_ggd, w, hb0, h1, gx, c, aa, lb,
               tid, wid, lane, mvmask, rowlane, out);
    __syncthreads();
    // final logits row 4094 from hbuf[1] = H_4095 (row 4095 stays zero)
    if (!rowlane) {
        const float d = dotsingle(w, hb1, 0.0f);
        const int cls = lane - 16;
        if (cls < NCLS) out[(TDEC - 2) * NCLS + cls] = d + lb;
    }
}

extern "C" void kernel_launch(void* const* d_in, const int* in_sizes, int n_in,
                              void* d_out, int out_size) {
    const float* x     = (const float*)d_in[0];
    const int*   y     = (const int*)  d_in[1];
    const float* eWih  = (const float*)d_in[2];
    const float* eWhh  = (const float*)d_in[3];
    const float* ebih  = (const float*)d_in[4];
    const float* ebhh  = (const float*)d_in[5];
    const float* dWih  = (const float*)d_in[6];
    const float* dWhh  = (const float*)d_in[7];
    const float* dbih  = (const float*)d_in[8];
    const float* dbhh  = (const float*)d_in[9];
    const float* linW  = (const float*)d_in[10];
    const float* linb  = (const float*)d_in[11];
    float* out = (float*)d_out;

    const int n = TENC * 400;
    gx_prep_kernel<<<(n + 255) / 256, 256>>>(x, y, eWih, ebih, ebhh,
                                             dWih, dbih, dbhh);
    lstm_encdec_kernel<<<1, NTH>>>(eWhh, dWhh, linW, linb, out);
}